// round 2
// baseline (speedup 1.0000x reference)
#include <cuda_runtime.h>
#include <cuda_bf16.h>
#include <math.h>

#define N_NODES 100000
#define E_MAX   1750000

// ---------------- scratch (device globals; no allocation allowed) ----------
__device__ float g_h   [N_NODES * 64];
__device__ float g_buf1[N_NODES * 64];
__device__ float g_buf2[N_NODES * 64];
__device__ float g_as  [N_NODES];
__device__ float g_ad  [N_NODES];
__device__ int   g_deg [N_NODES];
__device__ int   g_off [N_NODES + 1];
__device__ int   g_cur [N_NODES];
__device__ int   g_csr [E_MAX];
__device__ int   g_is32;   // 1 if edge_index is int32, 0 if int64

// ---------------- dtype detection ------------------------------------------
// int64 node ids < 2^31 have all-zero high (odd) 32-bit words; an int32 array
// of random ids in [0,1e5) almost surely has nonzero odd words.
__global__ void detect_kernel(const int* __restrict__ ei32, int nWords) {
    int lim = nWords < 4096 ? nWords : 4096;
    int any = 0;
    for (int i = 1; i < lim; i += 2) any |= (ei32[i] != 0);
    g_is32 = any ? 1 : 0;
}

__device__ __forceinline__ int load_idx(const int* ei32, const long long* ei64,
                                        int is32, int i) {
    return is32 ? ei32[i] : (int)ei64[i];
}

// ---------------- utility kernels ------------------------------------------
__global__ void zero_int_kernel(int* p, int n) {
    int i = blockIdx.x * blockDim.x + threadIdx.x;
    if (i < n) p[i] = 0;
}

__global__ void hist_kernel(const void* __restrict__ ei, int* __restrict__ deg,
                            int nE, int nN) {
    int i = blockIdx.x * blockDim.x + threadIdx.x;
    int nTot = nE + nN;
    if (i >= nTot) return;
    int is32 = g_is32;
    const int* e32 = (const int*)ei;
    const long long* e64 = (const long long*)ei;
    // dst row starts at element nE
    int d = (i < nE) ? load_idx(e32, e64, is32, nE + i) : (i - nE);
    atomicAdd(&deg[d], 1);
}

// single-block scan over N_NODES degrees -> exclusive offsets (+cursor copy)
__global__ void scan_kernel(const int* __restrict__ deg, int* __restrict__ off,
                            int* __restrict__ cur, int n) {
    __shared__ int sm[1024];
    __shared__ int s_carry;
    int tid = threadIdx.x;
    if (tid == 0) s_carry = 0;
    __syncthreads();
    for (int base = 0; base < n; base += 1024) {
        int i = base + tid;
        int v = (i < n) ? deg[i] : 0;
        sm[tid] = v;
        __syncthreads();
        #pragma unroll
        for (int s = 1; s < 1024; s <<= 1) {
            int t = (tid >= s) ? sm[tid - s] : 0;
            __syncthreads();
            sm[tid] += t;
            __syncthreads();
        }
        int excl = sm[tid] - v + s_carry;
        if (i < n) { off[i] = excl; cur[i] = excl; }
        int total = sm[1023];
        __syncthreads();
        if (tid == 0) s_carry += total;
        __syncthreads();
    }
    if (tid == 0) off[n] = s_carry;
}

__global__ void scatter_kernel(const void* __restrict__ ei,
                               int* __restrict__ cur, int* __restrict__ csr,
                               int nE, int nN) {
    int i = blockIdx.x * blockDim.x + threadIdx.x;
    int nTot = nE + nN;
    if (i >= nTot) return;
    int is32 = g_is32;
    const int* e32 = (const int*)ei;
    const long long* e64 = (const long long*)ei;
    int s, d;
    if (i < nE) {
        s = load_idx(e32, e64, is32, i);         // src row at [0, nE)
        d = load_idx(e32, e64, is32, nE + i);    // dst row at [nE, 2*nE)
    } else {
        s = d = i - nE;                           // self loops
    }
    int pos = atomicAdd(&cur[d], 1);
    csr[pos] = s;
}

// ---------------- GEMM: C[M,N] = A[M,K] @ B[K,N] ---------------------------
// block tile 128x64, K-step 16, thread tile 8x4, 256 threads
__global__ __launch_bounds__(256) void gemm_kernel(
    const float* __restrict__ A, const float* __restrict__ B,
    float* __restrict__ C, int M, int K, int N) {
    const int BM = 128, BN = 64, BK = 16, TM = 8, TN = 4;
    __shared__ float As[BK][BM + 1];
    __shared__ float Bs[BK][BN];
    int bm = blockIdx.x * BM;
    int tx = threadIdx.x % 16;
    int ty = threadIdx.x / 16;
    float acc[TM][TN] = {};
    for (int k0 = 0; k0 < K; k0 += BK) {
        // load A tile: 128x16
        {
            int kk = threadIdx.x % BK;
            int r0 = threadIdx.x / BK;   // 0..15
            #pragma unroll
            for (int i = 0; i < 8; i++) {
                int m = r0 + i * 16;
                int gm = bm + m;
                float v = 0.f;
                if (gm < M) v = A[(size_t)gm * K + k0 + kk];
                As[kk][m] = v;
            }
        }
        // load B tile: 16x64 (zero-pad cols >= N)
        {
            int n  = threadIdx.x % BN;   // 0..63
            int kr = threadIdx.x / BN;   // 0..3
            #pragma unroll
            for (int i = 0; i < 4; i++) {
                int kk = kr + i * 4;
                float v = 0.f;
                if (n < N) v = B[(size_t)(k0 + kk) * N + n];
                Bs[kk][n] = v;
            }
        }
        __syncthreads();
        #pragma unroll
        for (int kk = 0; kk < BK; ++kk) {
            float a[TM], b[TN];
            #pragma unroll
            for (int i = 0; i < TM; i++) a[i] = As[kk][ty * TM + i];
            #pragma unroll
            for (int j = 0; j < TN; j++) b[j] = Bs[kk][tx * TN + j];
            #pragma unroll
            for (int i = 0; i < TM; i++)
                #pragma unroll
                for (int j = 0; j < TN; j++) acc[i][j] += a[i] * b[j];
        }
        __syncthreads();
    }
    #pragma unroll
    for (int i = 0; i < TM; i++) {
        int gm = bm + ty * TM + i;
        if (gm >= M) continue;
        #pragma unroll
        for (int j = 0; j < TN; j++) {
            int n = tx * TN + j;
            if (n < N) C[(size_t)gm * N + n] = acc[i][j];
        }
    }
}

// ---------------- per-node attention logits: a_s, a_d ----------------------
template <int C>
__global__ void attn_reduce_kernel(const float* __restrict__ h,
                                   const float* __restrict__ asrc,
                                   const float* __restrict__ adst,
                                   float* __restrict__ as_, float* __restrict__ ad_,
                                   int nN) {
    int warp = (blockIdx.x * blockDim.x + threadIdx.x) >> 5;
    int lane = threadIdx.x & 31;
    if (warp >= nN) return;
    float s1 = 0.f, s2 = 0.f;
    #pragma unroll
    for (int c = lane; c < C; c += 32) {
        float hv = h[(size_t)warp * C + c];
        s1 += hv * asrc[c];
        s2 += hv * adst[c];
    }
    #pragma unroll
    for (int o = 16; o > 0; o >>= 1) {
        s1 += __shfl_down_sync(0xffffffffu, s1, o);
        s2 += __shfl_down_sync(0xffffffffu, s2, o);
    }
    if (lane == 0) { as_[warp] = s1; ad_[warp] = s2; }
}

// ---------------- fused segment-softmax + weighted aggregation -------------
// one warp per dst node; CSR gather, no atomics; bias + activation fused
template <int C, bool ACT>
__global__ void aggr_kernel(const int* __restrict__ off, const int* __restrict__ csr,
                            const float* __restrict__ h,
                            const float* __restrict__ as_, const float* __restrict__ ad_,
                            const float* __restrict__ bias,
                            float* __restrict__ out, int nN) {
    int warp = (blockIdx.x * blockDim.x + threadIdx.x) >> 5;
    int lane = threadIdx.x & 31;
    if (warp >= nN) return;
    int d = warp;
    int j   = off[d];
    int end = off[d + 1];
    float adv = ad_[d];
    float denom = 0.f;
    float acc0 = 0.f, acc1 = 0.f;
    for (; j < end; ++j) {
        int s = csr[j];
        float e = as_[s] + adv;
        e = (e > 0.f) ? e : 0.2f * e;
        float w = __expf(e);
        denom += w;
        if (C == 64) {
            float2 v = *(const float2*)(h + (size_t)s * 64 + 2 * lane);
            acc0 += w * v.x;
            acc1 += w * v.y;
        } else {
            float v = h[(size_t)s * 32 + lane];
            acc0 += w * v;
        }
    }
    float inv = 1.f / (denom + 1e-16f);
    if (C == 64) {
        float o0 = acc0 * inv + bias[2 * lane];
        float o1 = acc1 * inv + bias[2 * lane + 1];
        if (ACT) {
            o0 = (o0 > 0.f) ? o0 : 0.01f * o0;
            o1 = (o1 > 0.f) ? o1 : 0.01f * o1;
        }
        *(float2*)(out + (size_t)d * 64 + 2 * lane) = make_float2(o0, o1);
    } else {
        float o = acc0 * inv + bias[lane];
        if (ACT) o = (o > 0.f) ? o : 0.01f * o;
        out[(size_t)d * 32 + lane] = o;
    }
}

// ---------------- launch ----------------------------------------------------
extern "C" void kernel_launch(void* const* d_in, const int* in_sizes, int n_in,
                              void* d_out, int out_size) {
    const float* x   = (const float*)d_in[0];
    const void*  ei  = d_in[1];
    const float* W1  = (const float*)d_in[2];
    const float* as1 = (const float*)d_in[3];
    const float* ad1 = (const float*)d_in[4];
    const float* b1  = (const float*)d_in[5];
    const float* W2  = (const float*)d_in[6];
    const float* as2 = (const float*)d_in[7];
    const float* ad2 = (const float*)d_in[8];
    const float* b2  = (const float*)d_in[9];
    const float* W3  = (const float*)d_in[10];
    const float* as3 = (const float*)d_in[11];
    const float* ad3 = (const float*)d_in[12];
    const float* b3  = (const float*)d_in[13];
    float* out = (float*)d_out;

    int E    = in_sizes[1] / 2;      // element count is 2*E for both int32/int64
    int nTot = E + N_NODES;

    float *h, *buf1, *buf2, *pas, *pad;
    int *deg, *off, *cur, *csr;
    cudaGetSymbolAddress((void**)&h,    g_h);
    cudaGetSymbolAddress((void**)&buf1, g_buf1);
    cudaGetSymbolAddress((void**)&buf2, g_buf2);
    cudaGetSymbolAddress((void**)&pas,  g_as);
    cudaGetSymbolAddress((void**)&pad,  g_ad);
    cudaGetSymbolAddress((void**)&deg,  g_deg);
    cudaGetSymbolAddress((void**)&off,  g_off);
    cudaGetSymbolAddress((void**)&cur,  g_cur);
    cudaGetSymbolAddress((void**)&csr,  g_csr);

    // ---- detect int32 vs int64 edge_index, then build CSR by dst ----
    detect_kernel<<<1, 1>>>((const int*)ei, in_sizes[1]);
    zero_int_kernel<<<(N_NODES + 255) / 256, 256>>>(deg, N_NODES);
    hist_kernel<<<(nTot + 255) / 256, 256>>>(ei, deg, E, N_NODES);
    scan_kernel<<<1, 1024>>>(deg, off, cur, N_NODES);
    scatter_kernel<<<(nTot + 255) / 256, 256>>>(ei, cur, csr, E, N_NODES);

    int gemm_blocks = (N_NODES + 127) / 128;
    int node_warp_blocks = (N_NODES + 7) / 8;   // 256 threads = 8 warps

    // ---- layer 1: x[100k,256] @ W1[256,64] ----
    gemm_kernel<<<gemm_blocks, 256>>>(x, W1, h, N_NODES, 256, 64);
    attn_reduce_kernel<64><<<node_warp_blocks, 256>>>(h, as1, ad1, pas, pad, N_NODES);
    aggr_kernel<64, true><<<node_warp_blocks, 256>>>(off, csr, h, pas, pad, b1, buf1, N_NODES);

    // ---- layer 2: buf1[100k,64] @ W2[64,64] ----
    gemm_kernel<<<gemm_blocks, 256>>>(buf1, W2, h, N_NODES, 64, 64);
    attn_reduce_kernel<64><<<node_warp_blocks, 256>>>(h, as2, ad2, pas, pad, N_NODES);
    aggr_kernel<64, true><<<node_warp_blocks, 256>>>(off, csr, h, pas, pad, b2, buf2, N_NODES);

    // ---- layer 3: buf2[100k,64] @ W3[64,32] ----
    gemm_kernel<<<gemm_blocks, 256>>>(buf2, W3, h, N_NODES, 64, 32);
    attn_reduce_kernel<32><<<node_warp_blocks, 256>>>(h, as3, ad3, pas, pad, N_NODES);
    aggr_kernel<32, false><<<node_warp_blocks, 256>>>(off, csr, h, pas, pad, b3, out, N_NODES);
}

// round 3
// speedup vs baseline: 1.5977x; 1.5977x over previous
#include <cuda_runtime.h>
#include <cuda_bf16.h>
#include <math.h>

#define N_NODES 100000
#define E_MAX   1750000
#define SCAN_B  1024
#define SCAN_NB ((N_NODES + SCAN_B - 1) / SCAN_B)   // 98

// ---------------- scratch (device globals; no allocation allowed) ----------
__device__ float g_h   [N_NODES * 64];
__device__ float g_buf1[N_NODES * 64];
__device__ float g_buf2[N_NODES * 64];
__device__ float g_as  [N_NODES];
__device__ float g_ad  [N_NODES];
__device__ int   g_deg [N_NODES];
__device__ int   g_off [N_NODES + 1];
__device__ int   g_cur [N_NODES];
__device__ int   g_csr [E_MAX];
__device__ int   g_bsum[128];
__device__ int   g_is32;   // 1 if edge_index is int32, 0 if int64

// ---------------- dtype detection (parallel) --------------------------------
// int64 node ids < 2^31 have all-zero high (odd) 32-bit words; an int32 array
// of random ids in [0,1e5) almost surely has nonzero odd words.
__global__ void detect_kernel(const int* __restrict__ ei32, int nWords) {
    int lim = nWords < 65536 ? nWords : 65536;
    int any = 0;
    for (int i = 1 + 2 * threadIdx.x; i < lim; i += 2 * blockDim.x)
        any |= (ei32[i] != 0);
    any = __syncthreads_or(any);
    if (threadIdx.x == 0) g_is32 = any ? 1 : 0;
}

__device__ __forceinline__ int load_idx(const int* ei32, const long long* ei64,
                                        int is32, int i) {
    return is32 ? ei32[i] : (int)ei64[i];
}

// ---------------- CSR build --------------------------------------------------
__global__ void zero_int_kernel(int* p, int n) {
    int i = blockIdx.x * blockDim.x + threadIdx.x;
    if (i < n) p[i] = 0;
}

__global__ void hist_kernel(const void* __restrict__ ei, int* __restrict__ deg,
                            int nE, int nN) {
    int i = blockIdx.x * blockDim.x + threadIdx.x;
    int nTot = nE + nN;
    if (i >= nTot) return;
    int is32 = g_is32;
    const int* e32 = (const int*)ei;
    const long long* e64 = (const long long*)ei;
    int d = (i < nE) ? load_idx(e32, e64, is32, nE + i) : (i - nE);
    atomicAdd(&deg[d], 1);
}

// Phase A: per-block exclusive scan, emit block sums
__global__ void scanA_kernel(const int* __restrict__ deg, int* __restrict__ off,
                             int* __restrict__ bsum, int n) {
    __shared__ int sm[SCAN_B];
    int tid = threadIdx.x;
    int i = blockIdx.x * SCAN_B + tid;
    int v = (i < n) ? deg[i] : 0;
    sm[tid] = v;
    __syncthreads();
    #pragma unroll
    for (int s = 1; s < SCAN_B; s <<= 1) {
        int t = (tid >= s) ? sm[tid - s] : 0;
        __syncthreads();
        sm[tid] += t;
        __syncthreads();
    }
    if (i < n) off[i] = sm[tid] - v;     // local exclusive
    if (tid == SCAN_B - 1) bsum[blockIdx.x] = sm[tid];
}

// Phase B: exclusive scan of block sums (nb <= 128), set off[n] = total
__global__ void scanB_kernel(int* __restrict__ bsum, int nb,
                             int* __restrict__ off, int n) {
    __shared__ int sm[128];
    int tid = threadIdx.x;
    int v = (tid < nb) ? bsum[tid] : 0;
    sm[tid] = v;
    __syncthreads();
    #pragma unroll
    for (int s = 1; s < 128; s <<= 1) {
        int t = (tid >= s) ? sm[tid - s] : 0;
        __syncthreads();
        sm[tid] += t;
        __syncthreads();
    }
    if (tid < nb) bsum[tid] = sm[tid] - v;   // exclusive
    if (tid == 127) off[n] = sm[127];        // total
}

// Phase C: add block offsets, copy to cursor
__global__ void scanC_kernel(int* __restrict__ off, int* __restrict__ cur,
                             const int* __restrict__ bsum, int n) {
    int i = blockIdx.x * SCAN_B + threadIdx.x;
    if (i >= n) return;
    int v = off[i] + bsum[blockIdx.x];
    off[i] = v;
    cur[i] = v;
}

__global__ void scatter_kernel(const void* __restrict__ ei,
                               int* __restrict__ cur, int* __restrict__ csr,
                               int nE, int nN) {
    int i = blockIdx.x * blockDim.x + threadIdx.x;
    int nTot = nE + nN;
    if (i >= nTot) return;
    int is32 = g_is32;
    const int* e32 = (const int*)ei;
    const long long* e64 = (const long long*)ei;
    int s, d;
    if (i < nE) {
        s = load_idx(e32, e64, is32, i);
        d = load_idx(e32, e64, is32, nE + i);
    } else {
        s = d = i - nE;
    }
    int pos = atomicAdd(&cur[d], 1);
    csr[pos] = s;
}

// ---------------- GEMM + fused attention-logit epilogue ---------------------
// C[M,N] = A[M,K] @ B[K,N]; block tile 128x64, K-step 16, thread tile 8x4.
// Epilogue also computes as_[m] = sum_n C[m,n]*asrc[n], ad_ likewise
// (valid because BN >= N, so each block holds complete rows).
__global__ __launch_bounds__(256) void gemm_kernel(
    const float* __restrict__ A, const float* __restrict__ B,
    float* __restrict__ C, int M, int K, int N,
    const float* __restrict__ asrc, const float* __restrict__ adst,
    float* __restrict__ as_, float* __restrict__ ad_) {
    const int BM = 128, BN = 64, BK = 16, TM = 8, TN = 4;
    __shared__ float As[BK][BM + 1];
    __shared__ float Bs[BK][BN];
    int bm = blockIdx.x * BM;
    int tx = threadIdx.x % 16;
    int ty = threadIdx.x / 16;
    float acc[TM][TN] = {};
    for (int k0 = 0; k0 < K; k0 += BK) {
        {
            int kk = threadIdx.x % BK;
            int r0 = threadIdx.x / BK;
            #pragma unroll
            for (int i = 0; i < 8; i++) {
                int m = r0 + i * 16;
                int gm = bm + m;
                float v = 0.f;
                if (gm < M) v = A[(size_t)gm * K + k0 + kk];
                As[kk][m] = v;
            }
        }
        {
            int n  = threadIdx.x % BN;
            int kr = threadIdx.x / BN;
            #pragma unroll
            for (int i = 0; i < 4; i++) {
                int kk = kr + i * 4;
                float v = 0.f;
                if (n < N) v = B[(size_t)(k0 + kk) * N + n];
                Bs[kk][n] = v;
            }
        }
        __syncthreads();
        #pragma unroll
        for (int kk = 0; kk < BK; ++kk) {
            float a[TM], b[TN];
            #pragma unroll
            for (int i = 0; i < TM; i++) a[i] = As[kk][ty * TM + i];
            #pragma unroll
            for (int j = 0; j < TN; j++) b[j] = Bs[kk][tx * TN + j];
            #pragma unroll
            for (int i = 0; i < TM; i++)
                #pragma unroll
                for (int j = 0; j < TN; j++) acc[i][j] += a[i] * b[j];
        }
        __syncthreads();
    }
    // store C
    #pragma unroll
    for (int i = 0; i < TM; i++) {
        int gm = bm + ty * TM + i;
        if (gm >= M) continue;
        #pragma unroll
        for (int j = 0; j < TN; j++) {
            int n = tx * TN + j;
            if (n < N) C[(size_t)gm * N + n] = acc[i][j];
        }
    }
    // fused attention logits: reduce across the 16 tx lanes of each row
    #pragma unroll
    for (int i = 0; i < TM; i++) {
        float s1 = 0.f, s2 = 0.f;
        #pragma unroll
        for (int j = 0; j < TN; j++) {
            int n = tx * TN + j;
            if (n < N) {
                s1 += acc[i][j] * asrc[n];
                s2 += acc[i][j] * adst[n];
            }
        }
        #pragma unroll
        for (int o = 8; o > 0; o >>= 1) {
            s1 += __shfl_down_sync(0xffffffffu, s1, o, 16);
            s2 += __shfl_down_sync(0xffffffffu, s2, o, 16);
        }
        if (tx == 0) {
            int gm = bm + ty * TM + i;
            if (gm < M) { as_[gm] = s1; ad_[gm] = s2; }
        }
    }
}

// ---------------- fused segment-softmax + weighted aggregation --------------
// one warp per dst node; CSR gather, no atomics; bias + activation fused.
// 2-edge software pipeline for MLP=2 on the dependent csr->h chain.
template <int C, bool ACT>
__global__ void aggr_kernel(const int* __restrict__ off, const int* __restrict__ csr,
                            const float* __restrict__ h,
                            const float* __restrict__ as_, const float* __restrict__ ad_,
                            const float* __restrict__ bias,
                            float* __restrict__ out, int nN) {
    int warp = (blockIdx.x * blockDim.x + threadIdx.x) >> 5;
    int lane = threadIdx.x & 31;
    if (warp >= nN) return;
    int d = warp;
    int j   = off[d];
    int end = off[d + 1];
    float adv = ad_[d];
    float denom = 0.f;
    float acc0 = 0.f, acc1 = 0.f;
    for (; j + 1 < end; j += 2) {
        int s0 = csr[j];
        int s1 = csr[j + 1];
        float e0 = as_[s0] + adv;
        float e1 = as_[s1] + adv;
        e0 = (e0 > 0.f) ? e0 : 0.2f * e0;
        e1 = (e1 > 0.f) ? e1 : 0.2f * e1;
        float w0 = __expf(e0);
        float w1 = __expf(e1);
        denom += w0 + w1;
        if (C == 64) {
            float2 v0 = *(const float2*)(h + (size_t)s0 * 64 + 2 * lane);
            float2 v1 = *(const float2*)(h + (size_t)s1 * 64 + 2 * lane);
            acc0 += w0 * v0.x + w1 * v1.x;
            acc1 += w0 * v0.y + w1 * v1.y;
        } else {
            float v0 = h[(size_t)s0 * 32 + lane];
            float v1 = h[(size_t)s1 * 32 + lane];
            acc0 += w0 * v0 + w1 * v1;
        }
    }
    if (j < end) {
        int s = csr[j];
        float e = as_[s] + adv;
        e = (e > 0.f) ? e : 0.2f * e;
        float w = __expf(e);
        denom += w;
        if (C == 64) {
            float2 v = *(const float2*)(h + (size_t)s * 64 + 2 * lane);
            acc0 += w * v.x;
            acc1 += w * v.y;
        } else {
            float v = h[(size_t)s * 32 + lane];
            acc0 += w * v;
        }
    }
    float inv = 1.f / (denom + 1e-16f);
    if (C == 64) {
        float o0 = acc0 * inv + bias[2 * lane];
        float o1 = acc1 * inv + bias[2 * lane + 1];
        if (ACT) {
            o0 = (o0 > 0.f) ? o0 : 0.01f * o0;
            o1 = (o1 > 0.f) ? o1 : 0.01f * o1;
        }
        *(float2*)(out + (size_t)d * 64 + 2 * lane) = make_float2(o0, o1);
    } else {
        float o = acc0 * inv + bias[lane];
        if (ACT) o = (o > 0.f) ? o : 0.01f * o;
        out[(size_t)d * 32 + lane] = o;
    }
}

// ---------------- launch ----------------------------------------------------
extern "C" void kernel_launch(void* const* d_in, const int* in_sizes, int n_in,
                              void* d_out, int out_size) {
    const float* x   = (const float*)d_in[0];
    const void*  ei  = d_in[1];
    const float* W1  = (const float*)d_in[2];
    const float* as1 = (const float*)d_in[3];
    const float* ad1 = (const float*)d_in[4];
    const float* b1  = (const float*)d_in[5];
    const float* W2  = (const float*)d_in[6];
    const float* as2 = (const float*)d_in[7];
    const float* ad2 = (const float*)d_in[8];
    const float* b2  = (const float*)d_in[9];
    const float* W3  = (const float*)d_in[10];
    const float* as3 = (const float*)d_in[11];
    const float* ad3 = (const float*)d_in[12];
    const float* b3  = (const float*)d_in[13];
    float* out = (float*)d_out;

    int E    = in_sizes[1] / 2;
    int nTot = E + N_NODES;

    float *h, *buf1, *buf2, *pas, *pad;
    int *deg, *off, *cur, *csr, *bsum;
    cudaGetSymbolAddress((void**)&h,    g_h);
    cudaGetSymbolAddress((void**)&buf1, g_buf1);
    cudaGetSymbolAddress((void**)&buf2, g_buf2);
    cudaGetSymbolAddress((void**)&pas,  g_as);
    cudaGetSymbolAddress((void**)&pad,  g_ad);
    cudaGetSymbolAddress((void**)&deg,  g_deg);
    cudaGetSymbolAddress((void**)&off,  g_off);
    cudaGetSymbolAddress((void**)&cur,  g_cur);
    cudaGetSymbolAddress((void**)&csr,  g_csr);
    cudaGetSymbolAddress((void**)&bsum, g_bsum);

    // ---- detect dtype, build CSR by dst (shared across layers) ----
    detect_kernel<<<1, 256>>>((const int*)ei, in_sizes[1]);
    zero_int_kernel<<<(N_NODES + 255) / 256, 256>>>(deg, N_NODES);
    hist_kernel<<<(nTot + 255) / 256, 256>>>(ei, deg, E, N_NODES);
    scanA_kernel<<<SCAN_NB, SCAN_B>>>(deg, off, bsum, N_NODES);
    scanB_kernel<<<1, 128>>>(bsum, SCAN_NB, off, N_NODES);
    scanC_kernel<<<SCAN_NB, SCAN_B>>>(off, cur, bsum, N_NODES);
    scatter_kernel<<<(nTot + 255) / 256, 256>>>(ei, cur, csr, E, N_NODES);

    int gemm_blocks = (N_NODES + 127) / 128;
    int node_warp_blocks = (N_NODES + 7) / 8;

    // ---- layer 1 ----
    gemm_kernel<<<gemm_blocks, 256>>>(x, W1, h, N_NODES, 256, 64, as1, ad1, pas, pad);
    aggr_kernel<64, true><<<node_warp_blocks, 256>>>(off, csr, h, pas, pad, b1, buf1, N_NODES);

    // ---- layer 2 ----
    gemm_kernel<<<gemm_blocks, 256>>>(buf1, W2, h, N_NODES, 64, 64, as2, ad2, pas, pad);
    aggr_kernel<64, true><<<node_warp_blocks, 256>>>(off, csr, h, pas, pad, b2, buf2, N_NODES);

    // ---- layer 3 ----
    gemm_kernel<<<gemm_blocks, 256>>>(buf2, W3, h, N_NODES, 64, 32, as3, ad3, pas, pad);
    aggr_kernel<32, false><<<node_warp_blocks, 256>>>(off, csr, h, pas, pad, b3, out, N_NODES);
}